// round 9
// baseline (speedup 1.0000x reference)
#include <cuda_runtime.h>
#include <cuda_fp16.h>
#include <cuda_bf16.h>
#include <cstdint>

// Problem constants (fixed by the reference)
#define BB     2048
#define VV     2048
#define CC     512
#define MM     8
#define HH     16
#define EPSF   1e-6f
#define TPB    256          // threads per block (one channel each, 2 groups/row)
#define NCHAIN 222          // row chains: grid = 2*222 = 444 = 3 blocks/SM
#define NGRID  (2 * NCHAIN)

__device__ __forceinline__ float ex2_fast(float x) {
    float y;
    asm("ex2.approx.f32 %0, %1;" : "=f"(y) : "f"(x));
    return y;
}
__device__ __forceinline__ float rcp_fast(float x) {
    float y;
    asm("rcp.approx.f32 %0, %1;" : "=f"(y) : "f"(x));
    return y;
}
// Named *_fast to avoid colliding with cuda_fp16.hpp's h2tanh().
__device__ __forceinline__ __half2 h2tanh_fast(__half2 x) {
    unsigned xi = *reinterpret_cast<unsigned*>(&x), yi;
    asm("tanh.approx.f16x2 %0, %1;" : "=r"(yi) : "r"(xi));
    return *reinterpret_cast<__half2*>(&yi);
}
__device__ __forceinline__ void cpasync16(void* smem_ptr, const float* g) {
    unsigned int saddr = (unsigned int)__cvta_generic_to_shared(smem_ptr);
    asm volatile("cp.async.cg.shared.global [%0], [%1], 16;" :: "r"(saddr), "l"(g));
}
#define CP_COMMIT() asm volatile("cp.async.commit_group;" ::: "memory")
#define CP_WAIT0()  asm volatile("cp.async.wait_group 0;" ::: "memory")

// Occupancy-focused restructure: 256-thread blocks, 3 resident per SM
// (24 warps/SM vs the previous 16). Per-thread register footprint squeezed
// under the launch_bounds(256,3) cap of 85 by storing all weights packed
// TWO h-values per half2 register and unpacking in the loop (instructions
// are not the binder — rounds 5/6 proved that; registers are).
// Block layout: chain = blockIdx.x>>1 owns rows r = chain + k*NCHAIN;
// group = blockIdx.x&1 owns channels [group*256, group*256+256).
__global__ __launch_bounds__(TPB, 3) void gradoptim_attn_kernel(
    const float* __restrict__ preds,
    const int*   __restrict__ mask_ids,
    const float* __restrict__ W1,   // (C, 2, H)
    const float* __restrict__ b1,   // (C, H)
    const float* __restrict__ W2,   // (C, H)
    const float* __restrict__ b2,   // (C,)
    float*       __restrict__ out)  // (B, V)
{
    __shared__ float row[2][VV];    // double-buffered full row (8 KB each)

    const int t     = threadIdx.x;
    const int chain = blockIdx.x >> 1;
    const int group = blockIdx.x & 1;
    const int c     = group * TPB + t;       // this thread's channel

    // ---- Per-channel weights, packed 2 h-values per half2 register ----
    // pk[i] holds (h=2i, h=2i+1) in (lo, hi).
    __half2 w1a_pk[HH/2], w1b_pk[HH/2], b1_pk[HH/2], w2_pk[HH/2];
    {
        const float4* W1p = reinterpret_cast<const float4*>(W1 + (size_t)c * 2 * HH);
        const float4* b1p = reinterpret_cast<const float4*>(b1 + (size_t)c * HH);
        const float4* W2p = reinterpret_cast<const float4*>(W2 + (size_t)c * HH);
        #pragma unroll
        for (int i = 0; i < 4; i++) {
            float4 a  = W1p[i];       // W1[c,0,4i..4i+3]
            float4 bq = W1p[4 + i];   // W1[c,1,4i..4i+3]
            float4 bv = b1p[i];
            float4 w2 = W2p[i];
            w1a_pk[2*i]   = __floats2half2_rn(a.x,  a.y);
            w1a_pk[2*i+1] = __floats2half2_rn(a.z,  a.w);
            w1b_pk[2*i]   = __floats2half2_rn(bq.x, bq.y);
            w1b_pk[2*i+1] = __floats2half2_rn(bq.z, bq.w);
            b1_pk[2*i]    = __floats2half2_rn(bv.x, bv.y);
            b1_pk[2*i+1]  = __floats2half2_rn(bv.z, bv.w);
            w2_pk[2*i]    = __floats2half2_rn(w2.x, w2.y);
            w2_pk[2*i+1]  = __floats2half2_rn(w2.z, w2.w);
        }
    }
    const float b2c = b2[c];

    int idx[MM];
    {
        const int4* mi = reinterpret_cast<const int4*>(mask_ids + (size_t)c * MM);
        int4 i0 = mi[0], i1 = mi[1];
        idx[0] = i0.x; idx[1] = i0.y; idx[2] = i0.z; idx[3] = i0.w;
        idx[4] = i1.x; idx[5] = i1.y; idx[6] = i1.z; idx[7] = i1.w;
    }

    const float LOG2E = 1.4426950408889634f;

    // ---- Prologue: stage first row (full 2048 floats; 2 float4/thread) ----
    int r = chain;
    if (r < BB) {
        const float* src = preds + (size_t)r * VV;
        cpasync16(&row[0][t * 4],            src + t * 4);
        cpasync16(&row[0][(TPB + t) * 4],    src + (TPB + t) * 4);
        CP_COMMIT();
    }

    int buf = 0;
    while (r < BB) {
        CP_WAIT0();
        __syncthreads();

        // Prefetch next row into the other buffer (overlaps compute).
        const int rn = r + NCHAIN;
        if (rn < BB) {
            const float* src = preds + (size_t)rn * VV;
            cpasync16(&row[buf ^ 1][t * 4],         src + t * 4);
            cpasync16(&row[buf ^ 1][(TPB + t) * 4], src + (TPB + t) * 4);
            CP_COMMIT();
        }

        // Copy untouched tail columns [512,2048): 1536 floats = 384 float4,
        // split between the two groups (192 float4 each).
        {
            const int base4 = CC / 4 + group * 192;   // float4 index
            if (t < 192) {
                float4 v = reinterpret_cast<float4*>(row[buf])[base4 + t];
                reinterpret_cast<float4*>(out + (size_t)r * VV)[base4 + t] = v;
            }
        }

        // ---- Compute this thread's channel ----
        const float h_a = row[buf][c];
        float hm[MM];
        #pragma unroll
        for (int m = 0; m < MM; m++) hm[m] = row[buf][idx[m]];

        // u packed: lanes = (h=2i, h=2i+1); h_a broadcast to both lanes.
        const __half2 ha2 = __float2half2_rn(h_a);
        __half2 u_pk[HH/2];
        #pragma unroll
        for (int i = 0; i < HH/2; i++)
            u_pk[i] = __hfma2(ha2, w1a_pk[i], b1_pk[i]);

        // Scores: two m-values per half2 lane; weights unpacked per use.
        float sc[MM];
        #pragma unroll
        for (int p = 0; p < MM / 2; p++) {
            __half2 x2 = __floats2half2_rn(hm[2*p], hm[2*p + 1]);
            __half2 aE = __float2half2_rn(0.0f);
            __half2 aO = aE;
            #pragma unroll
            for (int i = 0; i < HH/2; i++) {
                __half2 uL = __low2half2(u_pk[i]),  uH = __high2half2(u_pk[i]);
                __half2 bL = __low2half2(w1b_pk[i]), bH = __high2half2(w1b_pk[i]);
                __half2 wL = __low2half2(w2_pk[i]),  wH = __high2half2(w2_pk[i]);
                aE = __hfma2(wL, h2tanh_fast(__hfma2(x2, bL, uL)), aE);
                aO = __hfma2(wH, h2tanh_fast(__hfma2(x2, bH, uH)), aO);
            }
            float2 fE = __half22float2(aE);
            float2 fO = __half22float2(aO);
            sc[2*p]     = (fE.x + fO.x) + b2c;
            sc[2*p + 1] = (fE.y + fO.y) + b2c;
        }

        // Softmax over m; weighted sum of h_m in full f32.
        float mx = sc[0];
        #pragma unroll
        for (int m = 1; m < MM; m++) mx = fmaxf(mx, sc[m]);

        float sum = 0.0f, ws = 0.0f;
        #pragma unroll
        for (int m = 0; m < MM; m++) {
            float e = ex2_fast((sc[m] - mx) * LOG2E);
            sum += e;
            ws   = fmaf(e, hm[m], ws);
        }
        const float corrected = fmaxf(h_a, ws * rcp_fast(sum) + EPSF);

        out[(size_t)r * VV + c] = corrected;

        buf ^= 1;
        r = rn;
    }
}

extern "C" void kernel_launch(void* const* d_in, const int* in_sizes, int n_in,
                              void* d_out, int out_size) {
    (void)in_sizes; (void)n_in; (void)out_size;
    const float* preds    = (const float*)d_in[0];
    // d_in[1] = ground_truth (unused by the reference)
    const int*   mask_ids = (const int*)  d_in[2];
    const float* W1       = (const float*)d_in[3];
    const float* b1       = (const float*)d_in[4];
    const float* W2       = (const float*)d_in[5];
    const float* b2       = (const float*)d_in[6];
    float*       out      = (float*)d_out;

    gradoptim_attn_kernel<<<NGRID, TPB>>>(preds, mask_ids, W1, b1, W2, b2, out);
}